// round 1
// baseline (speedup 1.0000x reference)
#include <cuda_runtime.h>
#include <cstdint>

// Embedding gather: out[token, :] = embedding[input_ids[token], :]
// input_ids: [2*2048] int32, embedding: [32000, 1024] fp32, out: [4096, 1024] fp32
//
// One CTA per token. 256 threads * float4 = 1024 floats = one row.
// Fully coalesced 16B loads/stores; pure HBM copy (~33.5 MB total traffic).

static constexpr int FEATURES = 1024;
static constexpr int VEC_PER_ROW = FEATURES / 4;   // 256 float4

__global__ void __launch_bounds__(256, 8)
embed_gather_kernel(const int* __restrict__ ids,
                    const float4* __restrict__ emb,
                    float4* __restrict__ out,
                    int n_tokens)
{
    int token = blockIdx.x;
    if (token >= n_tokens) return;
    int id = ids[token];          // broadcast read (L1 hit for all threads)
    const float4* src = emb + (size_t)id * VEC_PER_ROW;
    float4*       dst = out + (size_t)token * VEC_PER_ROW;
    dst[threadIdx.x] = __ldg(&src[threadIdx.x]);
}

extern "C" void kernel_launch(void* const* d_in, const int* in_sizes, int n_in,
                              void* d_out, int out_size)
{
    const int*    ids = (const int*)d_in[0];        // input_ids [2,2048]
    const float4* emb = (const float4*)d_in[1];     // embedding [32000,1024]
    float4*       out = (float4*)d_out;             // [2,2048,1024]

    int n_tokens = in_sizes[0];                     // 4096
    embed_gather_kernel<<<n_tokens, 256>>>(ids, emb, out, n_tokens);
}